// round 15
// baseline (speedup 1.0000x reference)
#include <cuda_runtime.h>

// logLikelihood_loss: sum over (B,T,P) of -log(clip(bivariate_gaussian_pdf, 1e-10)) / P
// B=64, T=128, P=512 -> 4,194,304 records. y_target: (...,3) f32, o_pred: (...,5) f32.
// HBM-bound streaming reduction. Log-domain formulation avoids exp/log round-trip.
//
// R14: (a) wave de-quantization. All prior variants had waves = 3.46 (total
//      threads / resident threads is invariant at 1 group/thread, 32 regs)
//      -> 13.5% tail loss. Now 8 records (2 float4-groups) per thread with ALL
//      16 LDG.128 front-loaded into distinct registers (preserves the R1 burst
//      property that the grid-stride versions destroyed). launch_bounds(256,3)
//      -> ~80 regs, occ 3, grid 2048, waves 4.61, tail loss 7.8%.
//      (b) keep R13's fire-and-forget red.relaxed tail (proven: occ 89, best
//      kernel time) but tighten the spinner (nanosleep 256 -> 64) to cut the
//      ~1us per-replay detection latency the harness timing exposed.

#define N_ELEM   4194304
#define THREADS  256
#define REC_PER_THREAD 8
#define BLOCKS   (N_ELEM / (THREADS * REC_PER_THREAD))   // 2048

// Fixed-point packing: bits [0:51) = (v + BIAS)*2^32 summed, bits [51:64) = count.
// Per-block v = block_sum/512, block covers 2048 records -> |v| <= 2048*23.03/512
// = 92.2; BIAS=128 keeps it positive. Max total: 2048*(128+92.2)*2^32 = 2^50.8
// < 2^51. Count: 2048 < 2^13. Winner resets word -> graph-replay-safe.
#define PACK_BIAS   128.0
#define PACK_SCALE  4294967296.0     // 2^32
#define CNT_SHIFT   51
#define SUM_MASK    ((1ULL << CNT_SHIFT) - 1)

__device__ unsigned long long g_pack = 0ULL;   // reset by spinner each run

// Accurate tanh from fast exp (independent of -use_fast_math's tanh.approx,
// whose abs error would poison 1-rho^2).
__device__ __forceinline__ float fast_tanh(float x) {
    float ax = fabsf(x);
    float e  = __expf(2.0f * ax);
    float t  = 1.0f - __fdividef(2.0f, e + 1.0f);
    return copysignf(t, x);
}

__global__ __launch_bounds__(THREADS, 3)   // 85-reg ceiling: room for 16 in-flight LDG.128
void nll_kernel(const float* __restrict__ y, const float* __restrict__ o,
                float* __restrict__ out) {
    const int t   = threadIdx.x;
    const size_t r0 = ((size_t)blockIdx.x * THREADS + t) * REC_PER_THREAD;  // first record

    // Front-load ALL inputs for 8 records: 10 float4 from o_pred (80 floats? no:
    // 8 records x 5 = 40 floats = 10 float4, contiguous) and 6 float4 from
    // y_target (8 x 3 = 24 floats). 16 independent LDG.128 issue back-to-back.
    const float4* o4 = reinterpret_cast<const float4*>(o + r0 * 5);
    const float4* y4 = reinterpret_cast<const float4*>(y + r0 * 3);

    float of[40], yf[24];
#pragma unroll
    for (int k = 0; k < 10; k++) reinterpret_cast<float4*>(of)[k] = o4[k];
#pragma unroll
    for (int k = 0; k < 6;  k++) reinterpret_cast<float4*>(yf)[k] = y4[k];

    const float LOG_2PI  = 1.8378770664093453f;   // ln(2*pi)
    const float CLAMP_HI = 23.025850929940457f;   // -ln(1e-10)

    float acc = 0.0f;
#pragma unroll
    for (int j = 0; j < REC_PER_THREAD; j++) {
        float mux = of[5 * j + 0];
        float muy = of[5 * j + 1];
        float lsx = of[5 * j + 2];   // log(sx)
        float lsy = of[5 * j + 3];   // log(sy)
        float cra = of[5 * j + 4];   // pre-tanh corr

        float y1 = yf[3 * j + 1];
        float y2 = yf[3 * j + 2];

        float inv_sx = __expf(-lsx);
        float inv_sy = __expf(-lsy);
        float nx = (y1 - mux) * inv_sx;
        float ny = (y2 - muy) * inv_sy;

        float tt = fast_tanh(cra);
        float om = fmaf(-tt, tt, 1.0f);            // 1 - rho^2 > 0
        float z  = fmaf(nx, nx, fmaf(ny, ny, -2.0f * tt * nx * ny));

        // -log pdf = z/(2*om) + log(2pi) + log(sx) + log(sy) + 0.5*log(om)
        float nll = 0.5f * __fdividef(z, om)
                  + (LOG_2PI + lsx + lsy + 0.5f * __logf(om));
        acc += fminf(nll, CLAMP_HI);               // == -log(clip(pdf, 1e-10))
    }

    // ── Block reduction ───────────────────────────────────────────────────
#pragma unroll
    for (int off = 16; off; off >>= 1)
        acc += __shfl_down_sync(0xffffffffu, acc, off);

    __shared__ float wsum[THREADS / 32];
    const int lane = t & 31;
    const int wid  = t >> 5;
    if (lane == 0) wsum[wid] = acc;
    __syncthreads();

    if (wid == 0) {
        float v = (lane < THREADS / 32) ? wsum[lane] : 0.0f;
#pragma unroll
        for (int off = 4; off; off >>= 1)
            v += __shfl_down_sync(0xffffffffu, v, off);

        if (lane == 0) {
            // Fire-and-forget RED of the packed contribution: no return trip,
            // block exits immediately -> wave turnover never stalls.
            double vb = (double)(v * (1.0f / 512.0f)) + PACK_BIAS;
            unsigned long long pack =
                (1ULL << CNT_SHIFT) | (unsigned long long)llrint(vb * PACK_SCALE);
            asm volatile("red.relaxed.gpu.global.add.u64 [%0], %1;"
                         :: "l"(&g_pack), "l"(pack) : "memory");

            // ── Spinner: one thread of block 0 finalizes (tight poll) ─────
            if (blockIdx.x == 0) {
                unsigned long long cur;
                do {
                    __nanosleep(64);
                    asm volatile("atom.relaxed.gpu.global.add.u64 %0, [%1], %2;"
                                 : "=l"(cur) : "l"(&g_pack), "l"(0ULL) : "memory");
                } while ((cur >> CNT_SHIFT) != (unsigned long long)BLOCKS);

                double s = (double)(cur & SUM_MASK) * (1.0 / PACK_SCALE)
                         - PACK_BIAS * (double)BLOCKS;
                out[0] = (float)s;
                atomicExch(&g_pack, 0ULL);   // reset for next graph replay
            }
        }
    }
}

extern "C" void kernel_launch(void* const* d_in, const int* in_sizes, int n_in,
                              void* d_out, int out_size) {
    const float* y = (const float*)d_in[0];   // y_target, 12,582,912 floats
    const float* o = (const float*)d_in[1];   // o_pred,  20,971,520 floats
    float* out = (float*)d_out;               // scalar fp32

    nll_kernel<<<BLOCKS, THREADS>>>(y, o, out);
}

// round 16
// speedup vs baseline: 1.1339x; 1.1339x over previous
#include <cuda_runtime.h>

// logLikelihood_loss: sum over (B,T,P) of -log(clip(bivariate_gaussian_pdf, 1e-10)) / P
// B=64, T=128, P=512 -> 4,194,304 records. y_target: (...,3) f32, o_pred: (...,5) f32.
// HBM-bound streaming reduction. Log-domain formulation avoids exp/log round-trip.
//
// R15: R14 (8 rec/thread, occ 3) regressed -> R1 compute shape confirmed
//      optimal (1 group/thread, 4096x256, 32 regs, occ 8). Keep R13's
//      fire-and-forget red.relaxed tail (best kernel: 24.5us, DRAM 71.3) and
//      fix its 1.9us total-vs-kernel gap: __nanosleep has coarse (~us)
//      scheduling granularity, so the spinner woke 1-2us after the last RED.
//      Busy-poll with back-to-back relaxed atom.add-0 instead (~318ns period,
//      ~75 polls total on one word -- noise), detection tail ~0.3us.

#define N_ELEM   4194304
#define GROUPS   (N_ELEM / 4)        // 4 records per thread
#define THREADS  256
#define BLOCKS   (GROUPS / THREADS)  // 4096

// Fixed-point packing: bits [0:51) = (v + BIAS)*2^32 summed, bits [51:64) = count.
// Per-block v = block_sum/512 in [-12, 46.1]; BIAS=64 keeps the field positive.
// Max total: 4096 * (64+46.1) * 2^32 = 2^50.8 < 2^51. Count: 4096 < 2^13.
#define PACK_BIAS   64.0
#define PACK_SCALE  4294967296.0     // 2^32
#define CNT_SHIFT   51
#define SUM_MASK    ((1ULL << CNT_SHIFT) - 1)

__device__ unsigned long long g_pack = 0ULL;   // reset by spinner each run

// Accurate tanh from fast exp (independent of -use_fast_math's tanh.approx,
// whose abs error would poison 1-rho^2).
__device__ __forceinline__ float fast_tanh(float x) {
    float ax = fabsf(x);
    float e  = __expf(2.0f * ax);
    float t  = 1.0f - __fdividef(2.0f, e + 1.0f);
    return copysignf(t, x);
}

__global__ __launch_bounds__(THREADS)
void nll_kernel(const float* __restrict__ y, const float* __restrict__ o,
                float* __restrict__ out) {
    const int g = blockIdx.x * blockDim.x + threadIdx.x;   // group of 4 records

    // Direct AoS loads: 5 float4 from o_pred, 3 float4 from y_target.
    // All 8 LDG.128 issue up front -> full-chip burst keeps DRAM saturated.
    const float4* o4 = reinterpret_cast<const float4*>(o) + (size_t)g * 5;
    const float4* y4 = reinterpret_cast<const float4*>(y) + (size_t)g * 3;

    float of[20], yf[12];
#pragma unroll
    for (int k = 0; k < 5; k++) reinterpret_cast<float4*>(of)[k] = o4[k];
#pragma unroll
    for (int k = 0; k < 3; k++) reinterpret_cast<float4*>(yf)[k] = y4[k];

    const float LOG_2PI  = 1.8378770664093453f;   // ln(2*pi)
    const float CLAMP_HI = 23.025850929940457f;   // -ln(1e-10)

    float acc = 0.0f;
#pragma unroll
    for (int j = 0; j < 4; j++) {
        float mux = of[5 * j + 0];
        float muy = of[5 * j + 1];
        float lsx = of[5 * j + 2];   // log(sx)
        float lsy = of[5 * j + 3];   // log(sy)
        float cra = of[5 * j + 4];   // pre-tanh corr

        float y1 = yf[3 * j + 1];
        float y2 = yf[3 * j + 2];

        float inv_sx = __expf(-lsx);
        float inv_sy = __expf(-lsy);
        float nx = (y1 - mux) * inv_sx;
        float ny = (y2 - muy) * inv_sy;

        float tt = fast_tanh(cra);
        float om = fmaf(-tt, tt, 1.0f);            // 1 - rho^2 > 0
        float z  = fmaf(nx, nx, fmaf(ny, ny, -2.0f * tt * nx * ny));

        // -log pdf = z/(2*om) + log(2pi) + log(sx) + log(sy) + 0.5*log(om)
        float nll = 0.5f * __fdividef(z, om)
                  + (LOG_2PI + lsx + lsy + 0.5f * __logf(om));
        acc += fminf(nll, CLAMP_HI);               // == -log(clip(pdf, 1e-10))
    }

    // ── Block reduction (identical to R1) ─────────────────────────────────
#pragma unroll
    for (int off = 16; off; off >>= 1)
        acc += __shfl_down_sync(0xffffffffu, acc, off);

    __shared__ float wsum[THREADS / 32];
    const int lane = threadIdx.x & 31;
    const int wid  = threadIdx.x >> 5;
    if (lane == 0) wsum[wid] = acc;
    __syncthreads();

    if (wid == 0) {
        float v = (lane < THREADS / 32) ? wsum[lane] : 0.0f;
#pragma unroll
        for (int off = 4; off; off >>= 1)
            v += __shfl_down_sync(0xffffffffu, v, off);

        if (lane == 0) {
            // Fire-and-forget RED of the packed contribution: no return trip,
            // block exits immediately -> wave turnover never stalls.
            double vb = (double)(v * (1.0f / 512.0f)) + PACK_BIAS;
            unsigned long long pack =
                (1ULL << CNT_SHIFT) | (unsigned long long)llrint(vb * PACK_SCALE);
            asm volatile("red.relaxed.gpu.global.add.u64 [%0], %1;"
                         :: "l"(&g_pack), "l"(pack) : "memory");

            // ── Spinner: one thread of block 0, pure atomic busy-poll ─────
            // (no __nanosleep: its ~us wakeup granularity cost 1.9us/replay)
            if (blockIdx.x == 0) {
                unsigned long long cur;
                do {
                    asm volatile("atom.relaxed.gpu.global.add.u64 %0, [%1], %2;"
                                 : "=l"(cur) : "l"(&g_pack), "l"(0ULL) : "memory");
                } while ((cur >> CNT_SHIFT) != (unsigned long long)BLOCKS);

                double s = (double)(cur & SUM_MASK) * (1.0 / PACK_SCALE)
                         - PACK_BIAS * (double)BLOCKS;
                out[0] = (float)s;
                atomicExch(&g_pack, 0ULL);   // reset for next graph replay
            }
        }
    }
}

extern "C" void kernel_launch(void* const* d_in, const int* in_sizes, int n_in,
                              void* d_out, int out_size) {
    const float* y = (const float*)d_in[0];   // y_target, 12,582,912 floats
    const float* o = (const float*)d_in[1];   // o_pred,  20,971,520 floats
    float* out = (float*)d_out;               // scalar fp32

    nll_kernel<<<BLOCKS, THREADS>>>(y, o, out);
}